// round 1
// baseline (speedup 1.0000x reference)
#include <cuda_runtime.h>

// RoIBridge: masked positional-embedding gather.
// out[row, c*64 + d] = obj[row]==1 ? table[idx(row,c), d] : 0
// idx = (int)clamp(frac[row,c] * 224, 0, 224)
// rows = 2048*128 = 262144, row width = 256 floats (4 coords x 64).
//
// HBM-write-bound: 268 MB output. One thread per float4 (16 B) of output.
// Warp = half a row -> uniform mask branch, coalesced 128-bit LD/ST.
// Table (57.6 KB) is L1-resident; no shared-memory staging (would multiply
// L2 fill traffic by the block count).

static constexpr int IMAGE_SIZE = 224;
static constexpr int ROWS = 2048 * 128;        // B * OBJ_TYPE_NUM
static constexpr int F4_PER_ROW = 64;          // 256 floats / 4

__global__ void __launch_bounds__(256, 8)
roibridge_kernel(const float* __restrict__ frac,     // [ROWS, 4]
                 const int* __restrict__ obj,        // [ROWS]
                 const float4* __restrict__ table4,  // [225, 16] float4 view
                 float4* __restrict__ out)           // [ROWS * 64] float4 view
{
    int tid = blockIdx.x * blockDim.x + threadIdx.x;  // 0 .. ROWS*64-1
    int row = tid >> 6;         // output row
    int j   = tid & 63;         // float4 index within row
    int c   = j >> 4;           // coordinate 0..3
    int d4  = j & 15;           // float4 within the 64-float coord embedding

    float4 v = make_float4(0.f, 0.f, 0.f, 0.f);
    if (__ldg(obj + row) == 1) {
        float f = __ldg(frac + row * 4 + c);
        float x = fminf(fmaxf(f * (float)IMAGE_SIZE, 0.0f), (float)IMAGE_SIZE);
        int idx = (int)x;                         // truncation toward zero, matches astype(int32)
        v = __ldg(table4 + idx * 16 + d4);        // L1-resident table row
    }
    out[tid] = v;
}

extern "C" void kernel_launch(void* const* d_in, const int* in_sizes, int n_in,
                              void* d_out, int out_size)
{
    const float*  frac  = (const float*)d_in[0];   // batch_fractional_bboxs [2048,128,4]
    const int*    obj   = (const int*)d_in[1];     // batch_obj_vecs [2048,128]
    const float*  table = (const float*)d_in[2];   // position_embedding_matrix [225,64]
    float4* out = (float4*)d_out;

    const int total_f4 = ROWS * F4_PER_ROW;        // 16,777,216
    const int threads = 256;
    const int blocks = total_f4 / threads;         // 65,536

    roibridge_kernel<<<blocks, threads>>>(frac, obj, (const float4*)table, out);
}

// round 5
// speedup vs baseline: 1.3607x; 1.3607x over previous
#include <cuda_runtime.h>

// RoIBridge: masked positional-embedding gather, latency-optimized.
// Thread t handles output row (t>>4), float4 lane d4 = t&15, across ALL 4
// coords: writes out[row*64 + c*16 + d4] for c=0..3.
//  - 1 obj load + 1 float4 frac load per thread (amortized over 64 B out)
//  - 4 independent L1-resident table loads (MLP=4)
//  - 4 streaming stores (__stcs: output is write-once, keep L2 for the table)
//  - each STG.128 is contiguous across the warp (lane j -> +j)
// Table (225x64 f32 = 57.6 KB) stays L1-resident; no smem staging.

static constexpr int IMAGE_SIZE = 224;
static constexpr int ROWS = 2048 * 128;     // 262144
static constexpr int LANES_PER_ROW = 16;    // one float4 lane per thread

__device__ __forceinline__ int clamp_idx(float f) {
    float x = fminf(fmaxf(f * (float)IMAGE_SIZE, 0.0f), (float)IMAGE_SIZE);
    return (int)x;   // trunc toward zero == astype(int32) for x >= 0
}

__global__ void __launch_bounds__(256, 8)
roibridge_kernel(const float4* __restrict__ frac4,   // [ROWS] (4 floats/row)
                 const int*    __restrict__ obj,     // [ROWS]
                 const float4* __restrict__ table4,  // [225 * 16]
                 float4*       __restrict__ out)     // [ROWS * 64]
{
    int tid = blockIdx.x * blockDim.x + threadIdx.x;   // 0 .. ROWS*16-1
    int row = tid >> 4;
    int d4  = tid & 15;

    const float4 z = make_float4(0.f, 0.f, 0.f, 0.f);
    float4 v0 = z, v1 = z, v2 = z, v3 = z;

    if (__ldg(obj + row) == 1) {
        float4 f = __ldg(frac4 + row);
        int i0 = clamp_idx(f.x);
        int i1 = clamp_idx(f.y);
        int i2 = clamp_idx(f.z);
        int i3 = clamp_idx(f.w);
        // 4 independent L1-resident gathers
        v0 = __ldg(table4 + i0 * 16 + d4);
        v1 = __ldg(table4 + i1 * 16 + d4);
        v2 = __ldg(table4 + i2 * 16 + d4);
        v3 = __ldg(table4 + i3 * 16 + d4);
    }

    float4* o = out + row * 64 + d4;
    __stcs(o +  0, v0);   // coord 0
    __stcs(o + 16, v1);   // coord 1
    __stcs(o + 32, v2);   // coord 2
    __stcs(o + 48, v3);   // coord 3
}

extern "C" void kernel_launch(void* const* d_in, const int* in_sizes, int n_in,
                              void* d_out, int out_size)
{
    const float4* frac4 = (const float4*)d_in[0];   // [2048,128,4] f32
    const int*    obj   = (const int*)d_in[1];      // [2048,128] i32
    const float4* table = (const float4*)d_in[2];   // [225,64] f32
    float4* out = (float4*)d_out;

    const int total = ROWS * LANES_PER_ROW;         // 4,194,304 threads
    const int threads = 256;
    const int blocks = total / threads;             // 16,384

    roibridge_kernel<<<blocks, threads>>>(frac4, obj, table, out);
}